// round 5
// baseline (speedup 1.0000x reference)
#include <cuda_runtime.h>
#include <math.h>
#include <stdint.h>

#define NB    4
#define CDIM  256
#define HWDIM 128
#define NPIX  (HWDIM*HWDIM)    // 16384
#define HEADS 8
#define NPTS  4
#define HP    (HEADS*NPTS)     // 32
#define OWCOLS 96              // 64 offset cols + 32 attention-weight cols

// ---------------- scratch (device globals; no allocation allowed) ----------------
__device__ float g_v  [(size_t)NB * NPIX * CDIM];          // (b, n, c) c = h*32 + j
__device__ float g_ow [(size_t)2 * NB * NPIX * OWCOLS];    // (q, b, n, 96)
__device__ float g_cat[(size_t)NB * NPIX * 2 * CDIM];      // (b, n, 512)
__device__ float g_w96[2 * CDIM * OWCOLS];                 // (q, k, 96) = [Woff | Waw]
__device__ float g_b96[2 * OWCOLS];

// ---------------- packed f32x2 helpers (constraints match ptx_helpers.cuh) ----------------
__device__ __forceinline__ uint64_t pack_dup_f32(float x) {
    uint64_t r; unsigned u = __float_as_uint(x);
    asm("mov.b64 %0, {%1, %1};" : "=l"(r) : "r"(u));
    return r;
}
__device__ __forceinline__ uint64_t ffma2(uint64_t a, uint64_t b, uint64_t c) {
    uint64_t d;
    asm("fma.rn.f32x2 %0, %1, %2, %3;" : "=l"(d) : "l"(a), "l"(b), "l"(c));
    return d;
}
__device__ __forceinline__ float2 unpack_f32x2(uint64_t v) {
    unsigned lo, hi;
    asm("mov.b64 {%0, %1}, %2;" : "=r"(lo), "=r"(hi) : "l"(v));
    return make_float2(__uint_as_float(lo), __uint_as_float(hi));
}

// ---------------- pack [Woff|Waw] into one 96-col weight per branch ----------------
__global__ void pack_w96_kernel(const float* __restrict__ Woff1, const float* __restrict__ Waw1,
                                const float* __restrict__ Woff2, const float* __restrict__ Waw2,
                                const float* __restrict__ boff1, const float* __restrict__ baw1,
                                const float* __restrict__ boff2, const float* __restrict__ baw2)
{
    int idx = blockIdx.x * blockDim.x + threadIdx.x;
    const int tot = 2 * CDIM * OWCOLS;
    if (idx < tot) {
        int q = idx / (CDIM * OWCOLS);
        int r = idx % (CDIM * OWCOLS);
        int k = r / OWCOLS;
        int j = r % OWCOLS;
        const float* Woff = q ? Woff2 : Woff1;
        const float* Waw  = q ? Waw2  : Waw1;
        g_w96[idx] = (j < 2 * HP) ? Woff[k * (2 * HP) + j] : Waw[k * HP + (j - 2 * HP)];
    }
    if (idx < 2 * OWCOLS) {
        int q = idx / OWCOLS;
        int j = idx % OWCOLS;
        const float* boff = q ? boff2 : boff1;
        const float* baw  = q ? baw2  : baw1;
        g_b96[idx] = (j < 2 * HP) ? boff[j] : baw[j - 2 * HP];
    }
}

// ---------------- generic fp32 SGEMM, 128x128x8 tile, 8x8 microtile ----------------
// Inner product uses packed f32x2 FFMA2: B packed in pairs along n, A duplicated.
// A_STRIDED:  A(m,k) = A[k*Astride + m]   (x tensors: (B,C,N), K along C)
// !A_STRIDED: A(m,k) = A[m*Astride + k]   (row-major, Astride = lda = K)
// TRANS_OUT=false: C[m*ldc + n]           TRANS_OUT=true: C[n*ldc + m] (n = channel)
template<bool A_STRIDED, bool TRANS_OUT, bool HAS_BIAS>
__global__ __launch_bounds__(256)
void sgemm_kernel(const float* __restrict__ A, const float* __restrict__ Bm,
                  const float* __restrict__ bias, float* __restrict__ C,
                  int Ncols, int K, int Astride,
                  size_t A_bstride, size_t C_bstride, int ldc)
{
    constexpr int BM = 128, BN = 128, BK = 8;
    __shared__ float As[BK][BM + 4];   // pitch 132 (mult of 4 -> float4-safe, kills store conflicts)
    __shared__ float Bs[BK][BN];

    const int b = blockIdx.z;
    A += (size_t)b * A_bstride;
    C += (size_t)b * C_bstride;
    const int m0 = blockIdx.x * BM;
    const int n0 = blockIdx.y * BN;
    const int tid = threadIdx.x;

    int mbase, nbase;
    if (TRANS_OUT) { mbase = (tid & 15) * 4; nbase = (tid >> 4) * 4; }
    else           { nbase = (tid & 15) * 4; mbase = (tid >> 4) * 4; }

    // 8 m-rows x 4 packed n-pairs (pair jp covers n columns {2jp, 2jp+1} of the
    // logical 8: jp 0,1 -> nbase..+3 ; jp 2,3 -> nbase+64..+67)
    uint64_t acc2[8][4];
#pragma unroll
    for (int i = 0; i < 8; i++)
#pragma unroll
        for (int jp = 0; jp < 4; jp++) acc2[i][jp] = 0ull;   // packed {0.f, 0.f}

    for (int k0 = 0; k0 < K; k0 += BK) {
        if (A_STRIDED) {
#pragma unroll
            for (int i = 0; i < 4; i++) {
                int e = tid + i * 256;
                int m = e & 127, k = e >> 7;
                As[k][m] = A[(size_t)(k0 + k) * Astride + (m0 + m)];
            }
        } else {
            int m  = tid >> 1;
            int kq = (tid & 1) * 4;
            float4 av = *(const float4*)(A + (size_t)(m0 + m) * Astride + (k0 + kq));
            As[kq + 0][m] = av.x; As[kq + 1][m] = av.y;
            As[kq + 2][m] = av.z; As[kq + 3][m] = av.w;
        }
#pragma unroll
        for (int i = 0; i < 4; i++) {
            int e = tid + i * 256;
            int n = e & 127, k = e >> 7;
            int gn = n0 + n;
            Bs[k][n] = (gn < Ncols) ? Bm[(size_t)(k0 + k) * Ncols + gn] : 0.f;
        }
        __syncthreads();
#pragma unroll
        for (int k = 0; k < BK; k++) {
            // B pairs straight from smem as 64-bit lanes (16B-aligned)
            ulonglong2 bp0 = *(const ulonglong2*)&Bs[k][nbase];
            ulonglong2 bp1 = *(const ulonglong2*)&Bs[k][nbase + 64];
            uint64_t b2[4] = {bp0.x, bp0.y, bp1.x, bp1.y};
            float4 a0 = *(const float4*)&As[k][mbase];
            float4 a1 = *(const float4*)&As[k][mbase + 64];
            float av[8] = {a0.x, a0.y, a0.z, a0.w, a1.x, a1.y, a1.z, a1.w};
#pragma unroll
            for (int i = 0; i < 8; i++) {
                uint64_t ad = pack_dup_f32(av[i]);
#pragma unroll
                for (int jp = 0; jp < 4; jp++)
                    acc2[i][jp] = ffma2(ad, b2[jp], acc2[i][jp]);
            }
        }
        __syncthreads();
    }

    // unpack to scalar 8x8 (lo half = even n within pair, matching layout)
    float acc[8][8];
#pragma unroll
    for (int i = 0; i < 8; i++)
#pragma unroll
        for (int jp = 0; jp < 4; jp++) {
            float2 u = unpack_f32x2(acc2[i][jp]);
            acc[i][2 * jp]     = u.x;
            acc[i][2 * jp + 1] = u.y;
        }

    if (!TRANS_OUT) {
        float bn[8];
#pragma unroll
        for (int j = 0; j < 8; j++) {
            int n = n0 + nbase + (j & 3) + ((j >> 2) ? 64 : 0);
            bn[j] = (HAS_BIAS && n < Ncols) ? bias[n] : 0.f;
        }
#pragma unroll
        for (int mi = 0; mi < 8; mi++) {
            int m = m0 + mbase + (mi & 3) + ((mi >> 2) ? 64 : 0);
            float* cr = C + (size_t)m * ldc;
            int n1 = n0 + nbase;
            if (n1 + 3 < Ncols) {
                *(float4*)&cr[n1] = make_float4(acc[mi][0] + bn[0], acc[mi][1] + bn[1],
                                                acc[mi][2] + bn[2], acc[mi][3] + bn[3]);
            } else {
#pragma unroll
                for (int j = 0; j < 4; j++)
                    if (n1 + j < Ncols) cr[n1 + j] = acc[mi][j] + bn[j];
            }
            int n2 = n1 + 64;
            if (n2 + 3 < Ncols) {
                *(float4*)&cr[n2] = make_float4(acc[mi][4] + bn[4], acc[mi][5] + bn[5],
                                                acc[mi][6] + bn[6], acc[mi][7] + bn[7]);
            } else {
#pragma unroll
                for (int j = 0; j < 4; j++)
                    if (n2 + j < Ncols) cr[n2 + j] = acc[mi][4 + j] + bn[4 + j];
            }
        }
    } else {
#pragma unroll
        for (int nj = 0; nj < 8; nj++) {
            int n = n0 + nbase + (nj & 3) + ((nj >> 2) ? 64 : 0);
            if (n < Ncols) {
                float bv = HAS_BIAS ? bias[n] : 0.f;
                float* cr = C + (size_t)n * ldc + m0;
                *(float4*)&cr[mbase] = make_float4(acc[0][nj] + bv, acc[1][nj] + bv,
                                                   acc[2][nj] + bv, acc[3][nj] + bv);
                *(float4*)&cr[mbase + 64] = make_float4(acc[4][nj] + bv, acc[5][nj] + bv,
                                                        acc[6][nj] + bv, acc[7][nj] + bv);
            }
        }
    }
}

// ---------------- fused softmax + bilinear sampling + weighted sum ----------------
// grid: (NPIX, NB, 2 branches), block: 256 (8 warps = 8 heads, 32 lanes = d)
__global__ __launch_bounds__(256) void sample_kernel()
{
    const int n = blockIdx.x;
    const int b = blockIdx.y;
    const int q = blockIdx.z;
    const int tid = threadIdx.x;
    const int h = tid >> 5;
    const int j = tid & 31;

    const float* __restrict__ owp =
        g_ow + ((size_t)q * NB * NPIX + (size_t)b * NPIX + n) * OWCOLS;

    // softmax over the 32 flattened (head, point) logits — each lane holds one
    float logit = owp[2 * HP + j];
    float mx = logit;
#pragma unroll
    for (int o = 16; o; o >>= 1) mx = fmaxf(mx, __shfl_xor_sync(0xffffffffu, mx, o));
    float ex = __expf(logit - mx);
    float sm = ex;
#pragma unroll
    for (int o = 16; o; o >>= 1) sm += __shfl_xor_sync(0xffffffffu, sm, o);
    float aw = ex / sm;

    const int px = n & (HWDIM - 1);
    const int py = n >> 7;
    // mirror reference arithmetic exactly to keep floor() decisions identical
    const float refx = ((float)px + 0.5f) / (float)HWDIM;
    const float refy = ((float)py + 0.5f) / (float)HWDIM;

    const float* __restrict__ vb = g_v + (size_t)b * NPIX * CDIM + h * 32 + j;
    const float2* __restrict__ offp = (const float2*)(owp + h * (2 * NPTS));
    float acc = 0.f;
#pragma unroll
    for (int p = 0; p < NPTS; p++) {
        float ax = __shfl_sync(0xffffffffu, aw, h * NPTS + p);
        float2 o2 = offp[p];
        float gx = 2.0f * (refx + o2.x) - 1.0f;
        float gy = 2.0f * (refy + o2.y) - 1.0f;
        float ix = ((gx + 1.0f) * (float)HWDIM - 1.0f) * 0.5f;
        float iy = ((gy + 1.0f) * (float)HWDIM - 1.0f) * 0.5f;
        float x0f = floorf(ix), y0f = floorf(iy);
        float wx1 = ix - x0f,   wy1 = iy - y0f;
        int x0 = (int)x0f, y0 = (int)y0f;
        float w00 = (1.f - wx1) * (1.f - wy1);
        float w10 = wx1 * (1.f - wy1);
        float w01 = (1.f - wx1) * wy1;
        float w11 = wx1 * wy1;
        float s = 0.f;
        if ((unsigned)x0 < HWDIM && (unsigned)y0 < HWDIM)
            s = fmaf(w00, vb[(size_t)(y0 * HWDIM + x0) * CDIM], s);
        if ((unsigned)(x0 + 1) < HWDIM && (unsigned)y0 < HWDIM)
            s = fmaf(w10, vb[(size_t)(y0 * HWDIM + x0 + 1) * CDIM], s);
        if ((unsigned)x0 < HWDIM && (unsigned)(y0 + 1) < HWDIM)
            s = fmaf(w01, vb[(size_t)((y0 + 1) * HWDIM + x0) * CDIM], s);
        if ((unsigned)(x0 + 1) < HWDIM && (unsigned)(y0 + 1) < HWDIM)
            s = fmaf(w11, vb[(size_t)((y0 + 1) * HWDIM + x0 + 1) * CDIM], s);
        acc = fmaf(ax, s, acc);
    }
    g_cat[((size_t)b * NPIX + n) * (2 * CDIM) + q * CDIM + h * 32 + j] = acc;
}

// ---------------- launch ----------------
extern "C" void kernel_launch(void* const* d_in, const int* in_sizes, int n_in,
                              void* d_out, int out_size)
{
    const float* x1    = (const float*)d_in[0];
    const float* x2    = (const float*)d_in[1];
    const float* x3    = (const float*)d_in[2];
    const float* Wv    = (const float*)d_in[3];
    const float* Woff1 = (const float*)d_in[4];
    const float* boff1 = (const float*)d_in[5];
    const float* Woff2 = (const float*)d_in[6];
    const float* boff2 = (const float*)d_in[7];
    const float* Waw1  = (const float*)d_in[8];
    const float* baw1  = (const float*)d_in[9];
    const float* Waw2  = (const float*)d_in[10];
    const float* baw2  = (const float*)d_in[11];
    const float* Wout  = (const float*)d_in[12];
    const float* bout  = (const float*)d_in[13];
    float* out = (float*)d_out;

    float *p_v, *p_ow, *p_cat, *p_w96, *p_b96;
    cudaGetSymbolAddress((void**)&p_v,   g_v);
    cudaGetSymbolAddress((void**)&p_ow,  g_ow);
    cudaGetSymbolAddress((void**)&p_cat, g_cat);
    cudaGetSymbolAddress((void**)&p_w96, g_w96);
    cudaGetSymbolAddress((void**)&p_b96, g_b96);

    // 1) pack branch weights into [Woff|Waw]
    pack_w96_kernel<<<(2 * CDIM * OWCOLS + 255) / 256, 256>>>(
        Woff1, Waw1, Woff2, Waw2, boff1, baw1, boff2, baw2);

    // 2) v = x3^T @ Wv   -> g_v (b, n, c)
    sgemm_kernel<true, false, false><<<dim3(NPIX / 128, CDIM / 128, NB), 256>>>(
        x3, Wv, nullptr, p_v,
        CDIM, CDIM, /*Astride=*/NPIX,
        (size_t)CDIM * NPIX, (size_t)NPIX * CDIM, /*ldc=*/CDIM);

    // 3) [off|aw] = x{1,2}^T @ W96 + b96 -> g_ow
    sgemm_kernel<true, false, true><<<dim3(NPIX / 128, 1, NB), 256>>>(
        x1, p_w96, p_b96, p_ow,
        OWCOLS, CDIM, NPIX,
        (size_t)CDIM * NPIX, (size_t)NPIX * OWCOLS, OWCOLS);
    sgemm_kernel<true, false, true><<<dim3(NPIX / 128, 1, NB), 256>>>(
        x2, p_w96 + CDIM * OWCOLS, p_b96 + OWCOLS, p_ow + (size_t)NB * NPIX * OWCOLS,
        OWCOLS, CDIM, NPIX,
        (size_t)CDIM * NPIX, (size_t)NPIX * OWCOLS, OWCOLS);

    // 4) softmax + bilinear sample + point-weighted sum -> g_cat (b, n, 512)
    sample_kernel<<<dim3(NPIX, NB, 2), 256>>>();

    // 5) out = cat @ Wout + bout, written transposed to (B, C, H, W)
    sgemm_kernel<false, true, true><<<dim3(NPIX / 128, CDIM / 128, NB), 256>>>(
        p_cat, Wout, bout, out,
        CDIM, 2 * CDIM, /*lda=*/2 * CDIM,
        (size_t)NPIX * 2 * CDIM, (size_t)CDIM * NPIX, /*ldc=*/NPIX);
}